// round 10
// baseline (speedup 1.0000x reference)
#include <cuda_runtime.h>

// SidNetLayer: N=50000, E=600000 per signed adjacency, D=128, K=10, C=0.15.
//   new_P = Ap*P + Am*M + 0.15*X
//   new_M = Am*P + Ap*M
// Merged signed CSR (sign in bit31), one warp per row. R10: EXPLICIT 4-edge
// software batching — per main-loop iteration the source issues 2 record
// LDG.128s + 8 gather LDG.128s before any FMA, forcing deep MLP that ptxas
// would not create from pragma unroll (R8/R9 evidence).

#define NMAX  50000
#define EMAX  600000
#define DD    128
#define DV    32          // D/4 float4 per row
#define KITER 10
#define CREST 0.15f

// ---------------- persistent device scratch --------------------------------
__device__ int  g_cnt[NMAX];      // zero at entry; scatter_k restores invariant
__device__ int  g_start[NMAX];    // exclusive row starts
__device__ int  g_cur[NMAX];      // scatter cursors (init = start)
__device__ int4 g_cv4[EMAX];      // 2E int2 records {col|bit31, valbits}, 16B-aligned
__device__ float g_PM[2][(size_t)2 * NMAX * DD];  // ping-pong, P then M

// ---------------- CSR build (3 launches) ------------------------------------
__global__ void hist_k(const int* __restrict__ rp, const int* __restrict__ rm, int E) {
    int i = blockIdx.x * blockDim.x + threadIdx.x;
    if (i < E) {
        atomicAdd(&g_cnt[rp[i]], 1);
        atomicAdd(&g_cnt[rm[i]], 1);
    }
}

__global__ void __launch_bounds__(1024)
scan_k(int n) {
    __shared__ int warp_inc[32];
    __shared__ int warp_off[32];
    __shared__ int red[32];
    __shared__ int sprefix;

    int tid  = threadIdx.x;
    int lane = tid & 31;
    int wid  = tid >> 5;
    int gid  = blockIdx.x * 1024 + tid;

    int v = (gid < n) ? g_cnt[gid] : 0;

    int x = v;
#pragma unroll
    for (int o = 1; o < 32; o <<= 1) {
        int y = __shfl_up_sync(0xffffffffu, x, o);
        if (lane >= o) x += y;
    }
    if (lane == 31) warp_inc[wid] = x;

    int ps = 0;
    int lim = blockIdx.x * 1024;
    for (int i = tid; i < lim; i += 1024) ps += g_cnt[i];
#pragma unroll
    for (int o = 16; o > 0; o >>= 1) ps += __shfl_down_sync(0xffffffffu, ps, o);
    if (lane == 0) red[wid] = ps;
    __syncthreads();

    if (tid < 32) {
        int s = warp_inc[tid];
        int t = s;
#pragma unroll
        for (int o = 1; o < 32; o <<= 1) {
            int y = __shfl_up_sync(0xffffffffu, t, o);
            if (tid >= o) t += y;
        }
        warp_off[tid] = t - s;
        int r = red[tid];
#pragma unroll
        for (int o = 16; o > 0; o >>= 1) r += __shfl_down_sync(0xffffffffu, r, o);
        if (tid == 0) sprefix = r;
    }
    __syncthreads();

    if (gid < n) {
        int st = sprefix + warp_off[wid] + (x - v);
        g_start[gid] = st;
        g_cur[gid]   = st;
    }
}

__global__ void scatter_k(const int* __restrict__ rp, const int* __restrict__ cp,
                          const float* __restrict__ vp,
                          const int* __restrict__ rm, const int* __restrict__ cm,
                          const float* __restrict__ vm, int E, int n) {
    int2* cv = (int2*)g_cv4;
    int i = blockIdx.x * blockDim.x + threadIdx.x;
    if (i < n) g_cnt[i] = 0;   // restore invariant for next call
    if (i >= E) return;
    int pos = atomicAdd(&g_cur[rp[i]], 1);
    cv[pos] = make_int2(cp[i], __float_as_int(vp[i]));
    pos = atomicAdd(&g_cur[rm[i]], 1);
    cv[pos] = make_int2(cm[i] | 0x80000000, __float_as_int(vm[i]));
}

// ---------------- fused diffusion iteration ---------------------------------
__global__ void __launch_bounds__(128)
diffuse_k(const float4* __restrict__ Ps, const float4* __restrict__ Ms,
          const float4* __restrict__ X4,
          float4* __restrict__ Pd, float4* __restrict__ Md,
          int n, int Etot) {
    int w = (blockIdx.x * blockDim.x + threadIdx.x) >> 5;
    unsigned lane = threadIdx.x & 31;
    if (w >= n) return;

    float4 x = __ldg(&X4[(unsigned)w * DV + lane]);
    float aP0 = CREST * x.x, aP1 = CREST * x.y, aP2 = CREST * x.z, aP3 = CREST * x.w;
    float aM0 = 0.f, aM1 = 0.f, aM2 = 0.f, aM3 = 0.f;

    int s = g_start[w];
    int e = (w + 1 < n) ? g_start[w + 1] : Etot;
    const int2* cvp = (const int2*)g_cv4;

#define EDGE1(CJ, VJ)                                                         \
    {                                                                         \
        unsigned off = (unsigned)((CJ) & 0x7fffffff) * DV + lane;             \
        const float4* A = ((CJ) < 0) ? Ms : Ps;                               \
        const float4* B = ((CJ) < 0) ? Ps : Ms;                               \
        float4 a = __ldg(&A[off]);                                            \
        float4 b = __ldg(&B[off]);                                            \
        aP0 += (VJ) * a.x; aP1 += (VJ) * a.y; aP2 += (VJ) * a.z; aP3 += (VJ) * a.w; \
        aM0 += (VJ) * b.x; aM1 += (VJ) * b.y; aM2 += (VJ) * b.z; aM3 += (VJ) * b.w; \
    }

    int j = s;
    // peel to even record index so int4 loads are 16B-aligned
    if (j < e && (j & 1)) {
        int2 cv = __ldg(&cvp[j]);
        EDGE1(cv.x, __int_as_float(cv.y));
        j++;
    }

    // main: 4 edges per iteration; all loads issued before any FMA
    for (; j + 4 <= e; j += 4) {
        int4 r0 = __ldg((const int4*)&cvp[j]);       // edges j, j+1
        int4 r1 = __ldg((const int4*)&cvp[j + 2]);   // edges j+2, j+3

        unsigned o0 = (unsigned)(r0.x & 0x7fffffff) * DV + lane;
        unsigned o1 = (unsigned)(r0.z & 0x7fffffff) * DV + lane;
        unsigned o2 = (unsigned)(r1.x & 0x7fffffff) * DV + lane;
        unsigned o3 = (unsigned)(r1.z & 0x7fffffff) * DV + lane;

        const float4* A0 = (r0.x < 0) ? Ms : Ps;  const float4* B0 = (r0.x < 0) ? Ps : Ms;
        const float4* A1 = (r0.z < 0) ? Ms : Ps;  const float4* B1 = (r0.z < 0) ? Ps : Ms;
        const float4* A2 = (r1.x < 0) ? Ms : Ps;  const float4* B2 = (r1.x < 0) ? Ps : Ms;
        const float4* A3 = (r1.z < 0) ? Ms : Ps;  const float4* B3 = (r1.z < 0) ? Ps : Ms;

        float4 a0 = __ldg(&A0[o0]);
        float4 b0 = __ldg(&B0[o0]);
        float4 a1 = __ldg(&A1[o1]);
        float4 b1 = __ldg(&B1[o1]);
        float4 a2 = __ldg(&A2[o2]);
        float4 b2 = __ldg(&B2[o2]);
        float4 a3 = __ldg(&A3[o3]);
        float4 b3 = __ldg(&B3[o3]);

        float v0 = __int_as_float(r0.y);
        float v1 = __int_as_float(r0.w);
        float v2 = __int_as_float(r1.y);
        float v3 = __int_as_float(r1.w);

        aP0 += v0 * a0.x; aP1 += v0 * a0.y; aP2 += v0 * a0.z; aP3 += v0 * a0.w;
        aM0 += v0 * b0.x; aM1 += v0 * b0.y; aM2 += v0 * b0.z; aM3 += v0 * b0.w;
        aP0 += v1 * a1.x; aP1 += v1 * a1.y; aP2 += v1 * a1.z; aP3 += v1 * a1.w;
        aM0 += v1 * b1.x; aM1 += v1 * b1.y; aM2 += v1 * b1.z; aM3 += v1 * b1.w;
        aP0 += v2 * a2.x; aP1 += v2 * a2.y; aP2 += v2 * a2.z; aP3 += v2 * a2.w;
        aM0 += v2 * b2.x; aM1 += v2 * b2.y; aM2 += v2 * b2.z; aM3 += v2 * b2.w;
        aP0 += v3 * a3.x; aP1 += v3 * a3.y; aP2 += v3 * a3.z; aP3 += v3 * a3.w;
        aM0 += v3 * b3.x; aM1 += v3 * b3.y; aM2 += v3 * b3.z; aM3 += v3 * b3.w;
    }

    // remainder (0-3 edges)
    for (; j < e; j++) {
        int2 cv = __ldg(&cvp[j]);
        EDGE1(cv.x, __int_as_float(cv.y));
    }
#undef EDGE1

    Pd[(unsigned)w * DV + lane] = make_float4(aP0, aP1, aP2, aP3);
    Md[(unsigned)w * DV + lane] = make_float4(aM0, aM1, aM2, aM3);
}

// ---------------- launch -----------------------------------------------------
extern "C" void kernel_launch(void* const* d_in, const int* in_sizes, int n_in,
                              void* d_out, int out_size) {
    const int*   rp = (const int*)d_in[0];
    const int*   cp = (const int*)d_in[1];
    const float* vp = (const float*)d_in[2];
    const int*   rm = (const int*)d_in[3];
    const int*   cm = (const int*)d_in[4];
    const float* vm = (const float*)d_in[5];
    const float* X  = (const float*)d_in[6];
    const float* M0 = (const float*)d_in[7];

    int E = in_sizes[0];
    int n = in_sizes[6] / DD;
    int Etot = 2 * E;

    hist_k<<<(E + 255) / 256, 256>>>(rp, rm, E);
    scan_k<<<(n + 1023) / 1024, 1024>>>(n);
    scatter_k<<<(E + 255) / 256, 256>>>(rp, cp, vp, rm, cm, vm, E, n);

    float* gPM = nullptr;
    cudaGetSymbolAddress((void**)&gPM, g_PM);

    const float* Ps = X;
    const float* Ms = M0;
    int grid = (n + 3) / 4;   // 4 warps / 128-thread block, 1 warp per row

    for (int it = 0; it < KITER; ++it) {
        float *Pd, *Md;
        if (it == KITER - 1) {
            Pd = (float*)d_out;
            Md = (float*)d_out + (size_t)n * DD;
        } else {
            int b = it & 1;
            float* basep = gPM + (size_t)b * 2 * NMAX * DD;
            Pd = basep;
            Md = basep + (size_t)n * DD;
        }
        diffuse_k<<<grid, 128>>>((const float4*)Ps, (const float4*)Ms,
                                 (const float4*)X, (float4*)Pd, (float4*)Md,
                                 n, Etot);
        Ps = Pd;
        Ms = Md;
    }
}

// round 11
// speedup vs baseline: 1.0875x; 1.0875x over previous
#include <cuda_runtime.h>

// SidNetLayer: N=50000, E=600000 per signed adjacency, D=128, K=10, C=0.15.
//   new_P = Ap*P + Am*M + 0.15*X
//   new_M = Am*P + Ap*M
// Merged signed CSR (sign in bit31 of col), packed {col,val} int2 records.
// R11: TWO rows per warp. One fused loop walks both rows' edge segments in
// lockstep -> two structurally independent load chains per warp (2 record
// LDG.64 + 4 gather LDG.128 in flight per iteration) without relying on
// ptxas to batch within a chain (R8/R9/R10 showed it never does).

#define NMAX  50000
#define EMAX  600000
#define DD    128
#define DV    32          // D/4 float4 per row
#define KITER 10
#define CREST 0.15f

// ---------------- persistent device scratch --------------------------------
__device__ int  g_cnt[NMAX];      // zero at entry; scatter_k restores invariant
__device__ int  g_start[NMAX];    // exclusive row starts
__device__ int  g_cur[NMAX];      // scatter cursors (init = start)
__device__ int2 g_cv[2 * EMAX];   // packed {col | bit31 sign, val bits}
__device__ float g_PM[2][(size_t)2 * NMAX * DD];  // ping-pong, P then M

// ---------------- CSR build (3 launches) ------------------------------------
__global__ void hist_k(const int* __restrict__ rp, const int* __restrict__ rm, int E) {
    int i = blockIdx.x * blockDim.x + threadIdx.x;
    if (i < E) {
        atomicAdd(&g_cnt[rp[i]], 1);
        atomicAdd(&g_cnt[rm[i]], 1);
    }
}

__global__ void __launch_bounds__(1024)
scan_k(int n) {
    __shared__ int warp_inc[32];
    __shared__ int warp_off[32];
    __shared__ int red[32];
    __shared__ int sprefix;

    int tid  = threadIdx.x;
    int lane = tid & 31;
    int wid  = tid >> 5;
    int gid  = blockIdx.x * 1024 + tid;

    int v = (gid < n) ? g_cnt[gid] : 0;

    int x = v;
#pragma unroll
    for (int o = 1; o < 32; o <<= 1) {
        int y = __shfl_up_sync(0xffffffffu, x, o);
        if (lane >= o) x += y;
    }
    if (lane == 31) warp_inc[wid] = x;

    int ps = 0;
    int lim = blockIdx.x * 1024;
    for (int i = tid; i < lim; i += 1024) ps += g_cnt[i];
#pragma unroll
    for (int o = 16; o > 0; o >>= 1) ps += __shfl_down_sync(0xffffffffu, ps, o);
    if (lane == 0) red[wid] = ps;
    __syncthreads();

    if (tid < 32) {
        int s = warp_inc[tid];
        int t = s;
#pragma unroll
        for (int o = 1; o < 32; o <<= 1) {
            int y = __shfl_up_sync(0xffffffffu, t, o);
            if (tid >= o) t += y;
        }
        warp_off[tid] = t - s;
        int r = red[tid];
#pragma unroll
        for (int o = 16; o > 0; o >>= 1) r += __shfl_down_sync(0xffffffffu, r, o);
        if (tid == 0) sprefix = r;
    }
    __syncthreads();

    if (gid < n) {
        int st = sprefix + warp_off[wid] + (x - v);
        g_start[gid] = st;
        g_cur[gid]   = st;
    }
}

__global__ void scatter_k(const int* __restrict__ rp, const int* __restrict__ cp,
                          const float* __restrict__ vp,
                          const int* __restrict__ rm, const int* __restrict__ cm,
                          const float* __restrict__ vm, int E, int n) {
    int i = blockIdx.x * blockDim.x + threadIdx.x;
    if (i < n) g_cnt[i] = 0;   // restore invariant for next call
    if (i >= E) return;
    int pos = atomicAdd(&g_cur[rp[i]], 1);
    g_cv[pos] = make_int2(cp[i], __float_as_int(vp[i]));
    pos = atomicAdd(&g_cur[rm[i]], 1);
    g_cv[pos] = make_int2(cm[i] | 0x80000000, __float_as_int(vm[i]));
}

// ---------------- fused diffusion iteration ---------------------------------
// One warp per TWO rows (2w, 2w+1). Per edge:
//   flag ? (accP += v*M[c], accM += v*P[c]) : (accP += v*P[c], accM += v*M[c])
__global__ void __launch_bounds__(128)
diffuse_k(const float4* __restrict__ Ps, const float4* __restrict__ Ms,
          const float4* __restrict__ X4,
          float4* __restrict__ Pd, float4* __restrict__ Md,
          int n, int Etot) {
    int w = (blockIdx.x * blockDim.x + threadIdx.x) >> 5;
    unsigned lane = threadIdx.x & 31;
    int rA = 2 * w;
    if (rA >= n) return;
    int rB = rA + 1;
    bool hasB = (rB < n);

    float4 xA = __ldg(&X4[(unsigned)rA * DV + lane]);
    float aP0 = CREST * xA.x, aP1 = CREST * xA.y, aP2 = CREST * xA.z, aP3 = CREST * xA.w;
    float aM0 = 0.f, aM1 = 0.f, aM2 = 0.f, aM3 = 0.f;
    float bP0 = 0.f, bP1 = 0.f, bP2 = 0.f, bP3 = 0.f;
    float bM0 = 0.f, bM1 = 0.f, bM2 = 0.f, bM3 = 0.f;
    if (hasB) {
        float4 xB = __ldg(&X4[(unsigned)rB * DV + lane]);
        bP0 = CREST * xB.x; bP1 = CREST * xB.y; bP2 = CREST * xB.z; bP3 = CREST * xB.w;
    }

    int sA = g_start[rA];
    int eA = (rB < n) ? g_start[rB] : Etot;
    int sB = hasB ? eA : 0;
    int eB = hasB ? ((rB + 1 < n) ? g_start[rB + 1] : Etot) : 0;

    // fused lockstep segment: two independent chains per iteration
    int cnt = min(eA - sA, eB - sB);
#pragma unroll 2
    for (int k = 0; k < cnt; k++) {
        int2 ca = __ldg(&g_cv[sA + k]);
        int2 cb = __ldg(&g_cv[sB + k]);
        float va = __int_as_float(ca.y);
        float vb = __int_as_float(cb.y);
        unsigned oa = (unsigned)(ca.x & 0x7fffffff) * DV + lane;
        unsigned ob = (unsigned)(cb.x & 0x7fffffff) * DV + lane;
        const float4* Aa = (ca.x < 0) ? Ms : Ps;
        const float4* Ba = (ca.x < 0) ? Ps : Ms;
        const float4* Ab = (cb.x < 0) ? Ms : Ps;
        const float4* Bb = (cb.x < 0) ? Ps : Ms;
        float4 a0 = __ldg(&Aa[oa]);
        float4 a1 = __ldg(&Ba[oa]);
        float4 b0 = __ldg(&Ab[ob]);
        float4 b1 = __ldg(&Bb[ob]);
        aP0 += va * a0.x; aP1 += va * a0.y; aP2 += va * a0.z; aP3 += va * a0.w;
        aM0 += va * a1.x; aM1 += va * a1.y; aM2 += va * a1.z; aM3 += va * a1.w;
        bP0 += vb * b0.x; bP1 += vb * b0.y; bP2 += vb * b0.z; bP3 += vb * b0.w;
        bM0 += vb * b1.x; bM1 += vb * b1.y; bM2 += vb * b1.z; bM3 += vb * b1.w;
    }
    sA += cnt;
    sB += cnt;

    // remainder of row A
#pragma unroll 2
    for (; sA < eA; sA++) {
        int2 cv = __ldg(&g_cv[sA]);
        float v = __int_as_float(cv.y);
        unsigned off = (unsigned)(cv.x & 0x7fffffff) * DV + lane;
        const float4* A = (cv.x < 0) ? Ms : Ps;
        const float4* B = (cv.x < 0) ? Ps : Ms;
        float4 a = __ldg(&A[off]);
        float4 b = __ldg(&B[off]);
        aP0 += v * a.x; aP1 += v * a.y; aP2 += v * a.z; aP3 += v * a.w;
        aM0 += v * b.x; aM1 += v * b.y; aM2 += v * b.z; aM3 += v * b.w;
    }
    // remainder of row B
#pragma unroll 2
    for (; sB < eB; sB++) {
        int2 cv = __ldg(&g_cv[sB]);
        float v = __int_as_float(cv.y);
        unsigned off = (unsigned)(cv.x & 0x7fffffff) * DV + lane;
        const float4* A = (cv.x < 0) ? Ms : Ps;
        const float4* B = (cv.x < 0) ? Ps : Ms;
        float4 a = __ldg(&A[off]);
        float4 b = __ldg(&B[off]);
        bP0 += v * a.x; bP1 += v * a.y; bP2 += v * a.z; bP3 += v * a.w;
        bM0 += v * b.x; bM1 += v * b.y; bM2 += v * b.z; bM3 += v * b.w;
    }

    Pd[(unsigned)rA * DV + lane] = make_float4(aP0, aP1, aP2, aP3);
    Md[(unsigned)rA * DV + lane] = make_float4(aM0, aM1, aM2, aM3);
    if (hasB) {
        Pd[(unsigned)rB * DV + lane] = make_float4(bP0, bP1, bP2, bP3);
        Md[(unsigned)rB * DV + lane] = make_float4(bM0, bM1, bM2, bM3);
    }
}

// ---------------- launch -----------------------------------------------------
extern "C" void kernel_launch(void* const* d_in, const int* in_sizes, int n_in,
                              void* d_out, int out_size) {
    const int*   rp = (const int*)d_in[0];
    const int*   cp = (const int*)d_in[1];
    const float* vp = (const float*)d_in[2];
    const int*   rm = (const int*)d_in[3];
    const int*   cm = (const int*)d_in[4];
    const float* vm = (const float*)d_in[5];
    const float* X  = (const float*)d_in[6];
    const float* M0 = (const float*)d_in[7];

    int E = in_sizes[0];
    int n = in_sizes[6] / DD;
    int Etot = 2 * E;

    hist_k<<<(E + 255) / 256, 256>>>(rp, rm, E);
    scan_k<<<(n + 1023) / 1024, 1024>>>(n);
    scatter_k<<<(E + 255) / 256, 256>>>(rp, cp, vp, rm, cm, vm, E, n);

    float* gPM = nullptr;
    cudaGetSymbolAddress((void**)&gPM, g_PM);

    const float* Ps = X;
    const float* Ms = M0;
    int nwarps = (n + 1) / 2;                 // one warp per two rows
    int grid = (nwarps * 32 + 127) / 128;     // 4 warps per 128-thread block

    for (int it = 0; it < KITER; ++it) {
        float *Pd, *Md;
        if (it == KITER - 1) {
            Pd = (float*)d_out;
            Md = (float*)d_out + (size_t)n * DD;
        } else {
            int b = it & 1;
            float* basep = gPM + (size_t)b * 2 * NMAX * DD;
            Pd = basep;
            Md = basep + (size_t)n * DD;
        }
        diffuse_k<<<grid, 128>>>((const float4*)Ps, (const float4*)Ms,
                                 (const float4*)X, (float4*)Pd, (float4*)Md,
                                 n, Etot);
        Ps = Pd;
        Ms = Md;
    }
}